// round 14
// baseline (speedup 1.0000x reference)
#include <cuda_runtime.h>
#include <cuda_fp16.h>
#include <cstdint>

#define D 256
#define P 8
#define B_GR 128
#define N_NODES 50000
#define N_EDGES 300000
#define NHB 148
#define MAX_TILES 3072
#define NCHUNK 8
#define WQ_CHUNK 8192                    // 256 n x 32 k int8 per chunk per level
#define WQ_HALF ((size_t)129 * NCHUNK * WQ_CHUNK)
#define N_ROWS_TOT (N_EDGES + N_NODES)

// smem offsets (per CTA: half tile M128 x N128, 512 threads)
#define OFF_INSTR 0
#define OFF_WVEC 512
#define OFF_SA 1024
#define OFF_SW 1536
#define OFF_RED 2048                     // 128 rows x 8 floats
#define OFF_A 6144                       // 2 buf x (hi,lo) x 128 rows x 48B
#define A_HL 6144
#define A_BUF 12288
#define OFF_W 30720                      // 2 buf x (hi,lo) x 128 n x 48B
#define W_HL 6144
#define W_BUF 12288
#define SMEM_NEED 55296

#define ZBLK ((N_NODES + 255) / 256)
#define WSBLK (D * D / 256)
#define AMAXBLK ((N_ROWS_TOT + 7) / 8)

// ---------------- device globals ----------------
__device__ __align__(256) char g_Wq[2 * WQ_HALF];
__device__ float g_wscale[129 * 256];
__device__ float g_amax_e[N_EDGES];
__device__ float g_amax_n[N_NODES];
__device__ float g_state_logits[N_NODES];
__device__ float g_rel_logits[N_NODES];
__device__ int g_eperm[N_EDGES];
__device__ int g_edst[N_EDGES];
__device__ float g_ecoef[N_EDGES];
__device__ int g_binstart[B_GR + 1];
__device__ int g_blockhist[NHB * B_GR];
__device__ int g_blockbase[NHB * B_GR];
__device__ int4 g_tiles[MAX_TILES];
__device__ int g_ntiles;

// ---------------- helpers ----------------
__device__ __forceinline__ uint32_t smem_u32(const void* p) {
    uint32_t a;
    asm("{ .reg .u64 t; cvta.to.shared.u64 t, %1; cvt.u32.u64 %0, t; }" : "=r"(a) : "l"(p));
    return a;
}
__device__ __forceinline__ void ldsm4(uint32_t* r, uint32_t addr) {
    asm volatile("ldmatrix.sync.aligned.m8n8.x4.shared.b16 {%0,%1,%2,%3}, [%4];"
                 : "=r"(r[0]), "=r"(r[1]), "=r"(r[2]), "=r"(r[3]) : "r"(addr));
}
__device__ __forceinline__ void imma16832(int* c, const uint32_t* a, uint32_t b0, uint32_t b1) {
    asm volatile(
        "mma.sync.aligned.m16n8k32.row.col.s32.s8.s8.s32 "
        "{%0,%1,%2,%3}, {%4,%5,%6,%7}, {%8,%9}, {%0,%1,%2,%3};"
        : "+r"(c[0]), "+r"(c[1]), "+r"(c[2]), "+r"(c[3])
        : "r"(a[0]), "r"(a[1]), "r"(a[2]), "r"(a[3]), "r"(b0), "r"(b1));
}
__device__ __forceinline__ void cpasync16(uint32_t saddr, const void* gaddr) {
    asm volatile("cp.async.cg.shared.global [%0], [%1], 16;" :: "r"(saddr), "l"(gaddr) : "memory");
}
__device__ __forceinline__ void cp_commit() { asm volatile("cp.async.commit_group;" ::: "memory"); }
__device__ __forceinline__ void cp_wait_all() { asm volatile("cp.async.wait_group 0;" ::: "memory"); }
__device__ __forceinline__ float elu1(float x) { return x > 0.f ? x : expm1f(x); }
__device__ __forceinline__ int q8(float v, float inv) {
    int h = __float2int_rn(v * inv);
    return max(-127, min(127, h));
}

// ---------------- L0: hist + zero ----------------
__global__ void __launch_bounds__(256) l0_kernel(const int* __restrict__ eb) {
    int blk = blockIdx.x;
    int t = threadIdx.x;
    if (blk < NHB) {
        __shared__ int h[B_GR];
        if (t < B_GR) h[t] = 0;
        __syncthreads();
        for (int e = blk * 256 + t; e < N_EDGES; e += NHB * 256)
            atomicAdd(&h[eb[e]], 1);
        __syncthreads();
        if (t < B_GR) g_blockhist[blk * B_GR + t] = h[t];
    } else {
        int i = (blk - NHB) * 256 + t;
        if (i < N_NODES) { g_rel_logits[i] = 0.f; g_state_logits[i] = 0.f; }
    }
}

// ---------------- L1: scan ----------------
__global__ void scan_kernel() {
    __shared__ int tot[B_GR];
    __shared__ int starts[B_GR + 1];
    int b = threadIdx.x;  // 128 threads
    int s = 0;
    for (int blk = 0; blk < NHB; blk++) s += g_blockhist[blk * B_GR + b];
    tot[b] = s;
    __syncthreads();
    if (b == 0) {
        int run = 0;
        for (int i = 0; i < B_GR; i++) { starts[i] = run; run += tot[i]; }
        starts[B_GR] = run;
        for (int i = 0; i <= B_GR; i++) g_binstart[i] = starts[i];
    }
    __syncthreads();
    {
        int run = starts[b];
        for (int blk = 0; blk < NHB; blk++) {
            g_blockbase[blk * B_GR + b] = run;
            run += g_blockhist[blk * B_GR + b];
        }
    }
}

__device__ __forceinline__ int lower_bound_dev(const int* __restrict__ a, int n, int key) {
    int lo = 0, hi = n;
    while (lo < hi) {
        int mid = (lo + hi) >> 1;
        if (a[mid] < key) lo = mid + 1; else hi = mid;
    }
    return lo;
}

// block-wide |w| max over 256 threads, quantize to 2-level int8, store.
__device__ void quant_store_w(int widx, int n, int k, float w, float* redbuf) {
    float m = fabsf(w);
#pragma unroll
    for (int o = 16; o > 0; o >>= 1) m = fmaxf(m, __shfl_xor_sync(0xFFFFFFFFu, m, o));
    if ((threadIdx.x & 31) == 0) redbuf[threadIdx.x >> 5] = m;
    __syncthreads();
    if (threadIdx.x < 32) {
        float mm = (threadIdx.x < 8) ? redbuf[threadIdx.x] : 0.f;
#pragma unroll
        for (int o = 4; o > 0; o >>= 1) mm = fmaxf(mm, __shfl_xor_sync(0xFFFFFFFFu, mm, o));
        if (threadIdx.x == 0) redbuf[0] = mm;
    }
    __syncthreads();
    float mx = redbuf[0];
    __syncthreads();  // free redbuf for next call
    float s = mx * (1.f / 127.f);
    float inv = mx > 0.f ? 127.f / mx : 0.f;
    int h = q8(w, inv);
    float resid = w - (float)h * s;
    int l = q8(resid * 128.f, inv);
    size_t idx = ((size_t)(widx * NCHUNK + (k >> 5)) * 256 + n) * 32 + (k & 31);
    g_Wq[idx] = (char)h;
    g_Wq[idx + WQ_HALF] = (char)l;
    if (k == 0) g_wscale[widx * 256 + n] = s;
}

// ---------------- L2: scatter + wquant + plan ----------------
__global__ void __launch_bounds__(256) l2_kernel(const int* __restrict__ eb,
                                                 const int* __restrict__ src,
                                                 const int* __restrict__ dst,
                                                 const float* __restrict__ dist,
                                                 const float* __restrict__ Wnp,
                                                 const float* __restrict__ We,
                                                 const float* __restrict__ sim,
                                                 const int* __restrict__ nidx) {
    int blk = blockIdx.x;
    int t = threadIdx.x;
    if (blk < NHB) {
        __shared__ int cur[B_GR];
        if (t < B_GR) cur[t] = g_blockbase[blk * B_GR + t];
        __syncthreads();
        for (int e = blk * 256 + t; e < N_EDGES; e += NHB * 256) {
            int b = eb[e];
            int pos = atomicAdd(&cur[b], 1);
            g_eperm[pos] = e;
            g_edst[pos] = dst[e];
            g_ecoef[pos] = dist[src[e]];
        }
    } else if (blk < NHB + WSBLK) {
        __shared__ float sim_s[B_GR * P];
        __shared__ float redbuf[8];
        for (int i = t; i < B_GR * P; i += 256) sim_s[i] = sim[i];
        __syncthreads();
        int n = blk - NHB;  // one n per block, k = t
        int k = t;
        float wp[P];
#pragma unroll
        for (int p = 0; p < P; p++) wp[p] = Wnp[p * (D * D) + n * D + k];
        quant_store_w(128, n, k, We[n * D + k], redbuf);
        for (int b = 0; b < B_GR; b++) {
            float a = 0.f;
#pragma unroll
            for (int p = 0; p < P; p++) a = fmaf(sim_s[b * P + p], wp[p], a);
            quant_store_w(b, n, k, a, redbuf);
        }
    } else {
        __shared__ int cnts[B_GR];
        __shared__ int starts[B_GR];
        __shared__ int info[B_GR][2];
        int b = t;
        if (b < B_GR) {
            int elo = g_binstart[b], ecnt = g_binstart[b + 1] - elo;
            int nlo = lower_bound_dev(nidx, N_NODES, b);
            int ncnt = lower_bound_dev(nidx, N_NODES, b + 1) - nlo;
            cnts[b] = ((ecnt + 127) >> 7) + ((ncnt + 127) >> 7);
            info[b][0] = elo;
            info[b][1] = nlo;
        }
        __syncthreads();
        if (t == 0) {
            int run = 0;
            for (int i = 0; i < B_GR; i++) { starts[i] = run; run += cnts[i]; }
            g_ntiles = run;
        }
        __syncthreads();
        if (b < B_GR) {
            int elo = info[b][0], ecnt = g_binstart[b + 1] - elo;
            int nlo = info[b][1];
            int ncnt = lower_bound_dev(nidx, N_NODES, b + 1) - nlo;
            int et = (ecnt + 127) >> 7, nt = (ncnt + 127) >> 7;
            int idx = starts[b];
            for (int k = 0; k < et; k++)
                g_tiles[idx++] = make_int4(128, b, elo + k * 128, min(128, ecnt - k * 128));
            for (int k = 0; k < nt; k++)
                g_tiles[idx++] = make_int4(b, b, nlo + k * 128, min(128, ncnt - k * 128));
        }
    }
}

// ---------------- L3: per-row amax (one warp per row) ----------------
__global__ void __launch_bounds__(256) amax_kernel(const float* __restrict__ edge_attrs,
                                                   const float* __restrict__ node_attrs) {
    int w = (blockIdx.x * 256 + threadIdx.x) >> 5;
    int lane = threadIdx.x & 31;
    if (w >= N_ROWS_TOT) return;
    const float* row = (w < N_EDGES) ? edge_attrs + (size_t)w * D
                                     : node_attrs + (size_t)(w - N_EDGES) * D;
    float4 v1 = __ldg((const float4*)row + lane);
    float4 v2 = __ldg((const float4*)row + 32 + lane);
    float m = fmaxf(fmaxf(fmaxf(fabsf(v1.x), fabsf(v1.y)), fmaxf(fabsf(v1.z), fabsf(v1.w))),
                    fmaxf(fmaxf(fabsf(v2.x), fabsf(v2.y)), fmaxf(fabsf(v2.z), fabsf(v2.w))));
#pragma unroll
    for (int o = 16; o > 0; o >>= 1) m = fmaxf(m, __shfl_xor_sync(0xFFFFFFFFu, m, o));
    if (lane == 0) {
        if (w < N_EDGES) g_amax_e[w] = m;
        else g_amax_n[w - N_EDGES] = m;
    }
}

// ---------------- L4: main IMMA kernel ----------------
// Half-tile per CTA: M128 x N128. 512 threads, 16 warps = 2 m-groups(M64) x 8 n-groups(N16).
__global__ void __launch_bounds__(512, 1) main_kernel(const float* __restrict__ node_attrs,
                                                      const float* __restrict__ edge_attrs,
                                                      const float* __restrict__ instr,
                                                      const float* __restrict__ w_node,
                                                      const float* __restrict__ w_rel) {
    extern __shared__ char smem[];
    const int tb = blockIdx.x >> 1;
    if (tb >= g_ntiles) return;
    const int half = blockIdx.x & 1;
    const int nofs = half * 128;
    const int4 ti = g_tiles[tb];
    const bool isEdge = (ti.x == 128);
    const int tid = threadIdx.x;
    const int lane = tid & 31;
    const int wid = tid >> 5;
    const int mgrp = wid & 1;    // M64 group
    const int ngrp = wid >> 1;   // 0..7, 16 cols each

    const uint32_t sb = smem_u32(smem);
    float* instr_s = (float*)(smem + OFF_INSTR);
    float* wvec_s = (float*)(smem + OFF_WVEC);
    float* sa_s = (float*)(smem + OFF_SA);
    float* sw_s = (float*)(smem + OFF_SW);
    float* red = (float*)(smem + OFF_RED);

    // A staging: 4 threads per row; thread covers 8 k-floats per chunk
    const int arow = tid >> 2;
    const int kq = (tid & 3) * 8;
    const bool valid = arow < ti.w;
    const float* rowsrc = node_attrs;
    if (valid)
        rowsrc = isEdge ? edge_attrs + (size_t)g_eperm[ti.z + arow] * D
                        : node_attrs + (size_t)(ti.z + arow) * D;

    const char* wq = g_Wq;
    const size_t wbase_g = ((size_t)ti.x * NCHUNK * 256 + nofs) * 32;

#define ISSUE_W(c, buf)                                                             \
    do {                                                                            \
        uint32_t wbb = sb + OFF_W + (buf) * W_BUF;                                  \
        size_t gb = wbase_g + (size_t)(c) * WQ_CHUNK;                               \
        int lvl = tid >> 8, row = (tid >> 1) & 127, g = tid & 1;                    \
        uint32_t d_ = wbb + lvl * W_HL + row * 48 + g * 16;                         \
        const char* s_ = wq + (size_t)lvl * WQ_HALF + gb + row * 32 + g * 16;       \
        cpasync16(d_, s_);                                                          \
        cp_commit();                                                                \
    } while (0)

    float4 va, vb;
#define LDG_A(c)                                                                    \
    do {                                                                            \
        if (valid) {                                                                \
            const float4* p_ = (const float4*)(rowsrc + (c) * 32 + kq);             \
            va = __ldg(p_);                                                         \
            vb = __ldg(p_ + 1);                                                     \
        } else {                                                                    \
            va = make_float4(0.f, 0.f, 0.f, 0.f);                                   \
            vb = va;                                                                \
        }                                                                           \
    } while (0)

#define STS_A(buf, s1, inv)                                                         \
    do {                                                                            \
        int h0 = q8(va.x, inv), h1 = q8(va.y, inv), h2 = q8(va.z, inv), h3 = q8(va.w, inv); \
        int h4 = q8(vb.x, inv), h5 = q8(vb.y, inv), h6 = q8(vb.z, inv), h7 = q8(vb.w, inv); \
        int l0 = q8((va.x - h0 * (s1)) * 128.f, inv), l1 = q8((va.y - h1 * (s1)) * 128.f, inv); \
        int l2 = q8((va.z - h2 * (s1)) * 128.f, inv), l3 = q8((va.w - h3 * (s1)) * 128.f, inv); \
        int l4 = q8((vb.x - h4 * (s1)) * 128.f, inv), l5 = q8((vb.y - h5 * (s1)) * 128.f, inv); \
        int l6 = q8((vb.z - h6 * (s1)) * 128.f, inv), l7 = q8((vb.w - h7 * (s1)) * 128.f, inv); \
        uint2 uh, ul;                                                               \
        uh.x = (h0 & 255) | ((h1 & 255) << 8) | ((h2 & 255) << 16) | ((uint32_t)(h3 & 255) << 24); \
        uh.y = (h4 & 255) | ((h5 & 255) << 8) | ((h6 & 255) << 16) | ((uint32_t)(h7 & 255) << 24); \
        ul.x = (l0 & 255) | ((l1 & 255) << 8) | ((l2 & 255) << 16) | ((uint32_t)(l3 & 255) << 24); \
        ul.y = (l4 & 255) | ((l5 & 255) << 8) | ((l6 & 255) << 16) | ((uint32_t)(l7 & 255) << 24); \
        char* ab_ = smem + OFF_A + (buf) * A_BUF + arow * 48 + kq;                  \
        *(uint2*)ab_ = uh;                                                          \
        *(uint2*)(ab_ + A_HL) = ul;                                                 \
    } while (0)

    // prologue
    ISSUE_W(0, 0);
    if (tid < 128) {
        instr_s[tid] = instr[ti.y * D + nofs + tid];
        wvec_s[tid] = (isEdge ? w_rel : w_node)[nofs + tid];
        sw_s[tid] = g_wscale[ti.x * 256 + nofs + tid];
        float am = 0.f;
        if (tid < ti.w) {
            int r = ti.z + tid;
            am = isEdge ? g_amax_e[g_eperm[r]] : g_amax_n[r];
        }
        sa_s[tid] = am * (1.f / 127.f);
    }
    LDG_A(0);
    __syncthreads();
    const float s1 = sa_s[arow];
    const float inv1 = s1 > 0.f ? 1.f / s1 : 0.f;
    STS_A(0, s1, inv1);

    int accH[4][2][4], accX[4][2][4];
#pragma unroll
    for (int a = 0; a < 4; a++)
#pragma unroll
        for (int b = 0; b < 2; b++)
#pragma unroll
            for (int c = 0; c < 4; c++) { accH[a][b][c] = 0; accX[a][b][c] = 0; }

#pragma unroll 1
    for (int c = 0; c < NCHUNK; c++) {
        cp_wait_all();
        __syncthreads();
        const int buf = c & 1;
        if (c + 1 < NCHUNK) {
            ISSUE_W(c + 1, buf ^ 1);  // safe: buf^1 last read in iter c-1, barrier passed
            LDG_A(c + 1);
        }
        const uint32_t abase = sb + OFF_A + buf * A_BUF;
        const uint32_t wbb = sb + OFF_W + buf * W_BUF;
        const uint32_t brow = wbb + (ngrp * 16 + (lane & 15)) * 48 + ((lane >> 4) * 16);
        uint32_t bh[4], bl[4];
        ldsm4(bh, brow);
        ldsm4(bl, brow + W_HL);
        // pass group 1: Ahi x Whi (main), Ahi x Wlo (cross)
#pragma unroll
        for (int mi = 0; mi < 4; mi++) {
            uint32_t ah[4];
            ldsm4(ah, abase + (mgrp * 64 + mi * 16 + (lane & 15)) * 48 + ((lane >> 4) * 16));
            imma16832(accH[mi][0], ah, bh[0], bh[2]);
            imma16832(accH[mi][1], ah, bh[1], bh[3]);
            imma16832(accX[mi][0], ah, bl[0], bl[2]);
            imma16832(accX[mi][1], ah, bl[1], bl[3]);
        }
        // pass group 2: Alo x Whi (cross)
#pragma unroll
        for (int mi = 0; mi < 4; mi++) {
            uint32_t al[4];
            ldsm4(al, abase + A_HL + (mgrp * 64 + mi * 16 + (lane & 15)) * 48 + ((lane >> 4) * 16));
            imma16832(accX[mi][0], al, bh[0], bh[2]);
            imma16832(accX[mi][1], al, bh[1], bh[3]);
        }
        if (c + 1 < NCHUNK) STS_A(buf ^ 1, s1, inv1);
    }

    // ---- epilogue ----
#pragma unroll
    for (int mi = 0; mi < 4; mi++) {
        const int r0 = mgrp * 64 + mi * 16 + (lane >> 2);
        const int r1 = r0 + 8;
        const float sa0 = sa_s[r0], sa1 = sa_s[r1];
        float pr0 = 0.f, pr1 = 0.f;
#pragma unroll
        for (int j = 0; j < 2; j++) {
            int c0 = ngrp * 16 + j * 8 + (lane & 3) * 2;
            float sw0 = sw_s[c0], sw1 = sw_s[c0 + 1];
            float w0 = wvec_s[c0], w1 = wvec_s[c0 + 1];
            float i0 = instr_s[c0], i1 = instr_s[c0 + 1];
            float x;
            x = sa0 * sw0 * ((float)accH[mi][j][0] + (float)accX[mi][j][0] * 0.0078125f);
            pr0 += w0 * elu1(i0 * x);
            x = sa0 * sw1 * ((float)accH[mi][j][1] + (float)accX[mi][j][1] * 0.0078125f);
            pr0 += w1 * elu1(i1 * x);
            x = sa1 * sw0 * ((float)accH[mi][j][2] + (float)accX[mi][j][2] * 0.0078125f);
            pr1 += w0 * elu1(i0 * x);
            x = sa1 * sw1 * ((float)accH[mi][j][3] + (float)accX[mi][j][3] * 0.0078125f);
            pr1 += w1 * elu1(i1 * x);
        }
        pr0 += __shfl_xor_sync(0xFFFFFFFFu, pr0, 1);
        pr0 += __shfl_xor_sync(0xFFFFFFFFu, pr0, 2);
        pr1 += __shfl_xor_sync(0xFFFFFFFFu, pr1, 1);
        pr1 += __shfl_xor_sync(0xFFFFFFFFu, pr1, 2);
        if ((lane & 3) == 0) {
            red[r0 * 8 + ngrp] = pr0;
            red[r1 * 8 + ngrp] = pr1;
        }
    }
    __syncthreads();
    if (tid < 128 && tid < ti.w) {
        float v = 0.f;
#pragma unroll
        for (int g = 0; g < 8; g++) v += red[tid * 8 + g];
        int gl = ti.z + tid;
        if (isEdge) atomicAdd(&g_rel_logits[g_edst[gl]], g_ecoef[gl] * v);
        else atomicAdd(&g_state_logits[gl], v);
    }
#undef ISSUE_W
#undef LDG_A
#undef STS_A
}

// ---------------- L5: segment softmax + combine ----------------
__global__ void __launch_bounds__(256) softmax_kernel(const int* __restrict__ nidx,
                                                      const float* __restrict__ rel_sim,
                                                      float* __restrict__ out) {
    const int b = blockIdx.x;
    const int t = threadIdx.x;
    __shared__ float sh[256];
    __shared__ int bounds[2];
    if (t == 0) {
        bounds[0] = lower_bound_dev(nidx, N_NODES, b);
        bounds[1] = lower_bound_dev(nidx, N_NODES, b + 1);
    }
    __syncthreads();
    const int lo = bounds[0], hi = bounds[1];
    if (hi <= lo) return;

    float m1 = -1e30f, m2 = -1e30f;
    for (int i = lo + t; i < hi; i += 256) {
        m1 = fmaxf(m1, g_state_logits[i]);
        m2 = fmaxf(m2, g_rel_logits[i]);
    }
    sh[t] = m1; __syncthreads();
    for (int o = 128; o > 0; o >>= 1) { if (t < o) sh[t] = fmaxf(sh[t], sh[t + o]); __syncthreads(); }
    m1 = sh[0]; __syncthreads();
    sh[t] = m2; __syncthreads();
    for (int o = 128; o > 0; o >>= 1) { if (t < o) sh[t] = fmaxf(sh[t], sh[t + o]); __syncthreads(); }
    m2 = sh[0]; __syncthreads();

    float s1 = 0.f, s2 = 0.f;
    for (int i = lo + t; i < hi; i += 256) {
        s1 += expf(g_state_logits[i] - m1);
        s2 += expf(g_rel_logits[i] - m2);
    }
    sh[t] = s1; __syncthreads();
    for (int o = 128; o > 0; o >>= 1) { if (t < o) sh[t] += sh[t + o]; __syncthreads(); }
    s1 = sh[0]; __syncthreads();
    sh[t] = s2; __syncthreads();
    for (int o = 128; o > 0; o >>= 1) { if (t < o) sh[t] += sh[t + o]; __syncthreads(); }
    s2 = sh[0]; __syncthreads();

    const float r = rel_sim[b];
    const float inv1 = 1.f / s1, inv2 = 1.f / s2;
    for (int i = lo + t; i < hi; i += 256) {
        float ns = expf(g_state_logits[i] - m1) * inv1;
        float nr = expf(g_rel_logits[i] - m2) * inv2;
        out[i] = r * nr + (1.f - r) * ns;
    }
}

extern "C" void kernel_launch(void* const* d_in, const int* in_sizes, int n_in,
                              void* d_out, int out_size) {
    const float* instr        = (const float*)d_in[0];
    const float* distribution = (const float*)d_in[1];
    const float* sim          = (const float*)d_in[2];
    const float* rel_sim      = (const float*)d_in[3];
    const float* node_attrs   = (const float*)d_in[4];
    const float* edge_attrs   = (const float*)d_in[5];
    const float* Wnp          = (const float*)d_in[6];
    const float* We           = (const float*)d_in[7];
    const float* w_node       = (const float*)d_in[8];
    const float* w_rel        = (const float*)d_in[9];
    const int*   node_indices = (const int*)d_in[10];
    const int*   edge_batch   = (const int*)d_in[11];
    const int*   ei           = (const int*)d_in[12];
    float* out = (float*)d_out;

    cudaFuncSetAttribute(main_kernel, cudaFuncAttributeMaxDynamicSharedMemorySize, SMEM_NEED);

    l0_kernel<<<NHB + ZBLK, 256>>>(edge_batch);
    scan_kernel<<<1, 128>>>();
    l2_kernel<<<NHB + WSBLK + 1, 256>>>(edge_batch, ei, ei + N_EDGES, distribution,
                                        Wnp, We, sim, node_indices);
    amax_kernel<<<AMAXBLK, 256>>>(edge_attrs, node_attrs);
    main_kernel<<<2 * MAX_TILES, 512, SMEM_NEED>>>(node_attrs, edge_attrs, instr,
                                                   w_node, w_rel);
    softmax_kernel<<<B_GR, 256>>>(node_indices, rel_sim, out);
}